// round 12
// baseline (speedup 1.0000x reference)
#include <cuda_runtime.h>
#include <cuda_bf16.h>
#include <cstdint>

// Embedding gather: out[r, :] = weight[indices[r], :]
// indices: [819200] int32, weight: [1,000,000 x 128] f32, out: [819200 x 128] f32.
//
// R3:  MLP=1 -> DRAM 59.7%, 164us (latency-limited at ~25KB/SM knee)
// R10: UNROLL=4 front-batched -> DRAM 80.4%, 123.2us (theory confirmed)
// R11/R12: UNROLL=8 -> double per-warp in-flight wavefronts to smooth the
//      DRAM latency tail / L1tex queue. launch_bounds(256,4) allows ~64 regs.
//      Predict DRAM -> 86-90%, dur -> ~110us. (R11 bench timed out; resubmit.)

#define UNROLL 8

__global__ __launch_bounds__(256, 4)
void embedding_gather_kernel(const int* __restrict__ indices,
                             const float4* __restrict__ weight,
                             float4* __restrict__ out,
                             int total_chunks)
{
    int tid    = blockIdx.x * blockDim.x + threadIdx.x;
    int stride = gridDim.x * blockDim.x;       // = total_chunks / UNROLL (exact)

    int    c[UNROLL];
    int    src[UNROLL];
    float4 v[UNROLL];

    #pragma unroll
    for (int u = 0; u < UNROLL; u++) {
        c[u] = tid + u * stride;
        int row  = c[u] >> 5;                  // 32 float4 chunks per 128-f32 row
        int lane = c[u] & 31;
        int idx  = __ldg(&indices[row]);       // warp-uniform broadcast
        src[u] = idx * 32 + lane;              // < 32M, fits int32
    }

    // Front-batched independent loads: 8 x 512B wavefronts in flight per warp
    #pragma unroll
    for (int u = 0; u < UNROLL; u++)
        v[u] = __ldg(&weight[src[u]]);

    #pragma unroll
    for (int u = 0; u < UNROLL; u++)
        __stcs(&out[c[u]], v[u]);              // streaming store: keep L2 for weight
}

extern "C" void kernel_launch(void* const* d_in, const int* in_sizes, int n_in,
                              void* d_out, int out_size)
{
    const int* indices = nullptr;
    const float4* weight = nullptr;
    int num_rows = 0;

    // Robust to either input ordering: indices is the small int32 array.
    if (in_sizes[0] < in_sizes[1]) {
        indices = (const int*)d_in[0];
        weight  = (const float4*)d_in[1];
        num_rows = in_sizes[0];
    } else {
        indices = (const int*)d_in[1];
        weight  = (const float4*)d_in[0];
        num_rows = in_sizes[1];
    }

    float4* out = (float4*)d_out;

    int total_chunks = num_rows * 32;          // 26,214,400 for the bench shape
    int block = 256;
    // 26,214,400 = 256 * 8 * 12800 -> exact division, no tail guard needed
    int grid = total_chunks / (block * UNROLL);

    embedding_gather_kernel<<<grid, block>>>(indices, weight, out, total_chunks);
}

// round 15
// speedup vs baseline: 1.0039x; 1.0039x over previous
#include <cuda_runtime.h>
#include <cuda_bf16.h>
#include <cstdint>

// Embedding gather: out[r, :] = weight[indices[r], :]
// indices: [819200] int32, weight: [1,000,000 x 128] f32, out: [819200 x 128] f32.
//
// R3:  MLP=1            -> DRAM 59.7%, 164us   (latency-limited)
// R10: MLP=4, occ 83%   -> DRAM 80.4%, 123.2us (knee cleared)
// R12: MLP=8, occ 44%   -> DRAM 79.8%, 123.6us (flat -> BW-ceiling regime ~6.35TB/s)
// R13-R15: probe the last corner: MLP=4 AND full occupancy (block=512,
//      lb(512,4), regs ~30 -> 2048 resident threads/SM, ~2x R12 in-flight).
//      Predict: DRAM -> 82-84% / ~119us if any latency slack remains,
//      else flat ~123us -> hard ceiling confirmed. (R13/R14 benches timed out.)

#define UNROLL 4

__global__ __launch_bounds__(512, 4)
void embedding_gather_kernel(const int* __restrict__ indices,
                             const float4* __restrict__ weight,
                             float4* __restrict__ out,
                             int total_chunks)
{
    int tid    = blockIdx.x * blockDim.x + threadIdx.x;
    int stride = gridDim.x * blockDim.x;       // = total_chunks / UNROLL (exact)

    int    c[UNROLL];
    int    src[UNROLL];
    float4 v[UNROLL];

    #pragma unroll
    for (int u = 0; u < UNROLL; u++) {
        c[u] = tid + u * stride;
        int row  = c[u] >> 5;                  // 32 float4 chunks per 128-f32 row
        int lane = c[u] & 31;
        int idx  = __ldg(&indices[row]);       // warp-uniform broadcast
        src[u] = idx * 32 + lane;              // < 32M, fits int32
    }

    // Front-batched independent loads: 4 x 512B wavefronts in flight per warp
    #pragma unroll
    for (int u = 0; u < UNROLL; u++)
        v[u] = __ldg(&weight[src[u]]);

    #pragma unroll
    for (int u = 0; u < UNROLL; u++)
        __stcs(&out[c[u]], v[u]);              // streaming store: keep L2 for weight
}

extern "C" void kernel_launch(void* const* d_in, const int* in_sizes, int n_in,
                              void* d_out, int out_size)
{
    const int* indices = nullptr;
    const float4* weight = nullptr;
    int num_rows = 0;

    // Robust to either input ordering: indices is the small int32 array.
    if (in_sizes[0] < in_sizes[1]) {
        indices = (const int*)d_in[0];
        weight  = (const float4*)d_in[1];
        num_rows = in_sizes[0];
    } else {
        indices = (const int*)d_in[1];
        weight  = (const float4*)d_in[0];
        num_rows = in_sizes[1];
    }

    float4* out = (float4*)d_out;

    int total_chunks = num_rows * 32;          // 26,214,400 for the bench shape
    int block = 512;
    // 26,214,400 = 512 * 4 * 12800 -> exact division, no tail guard needed
    int grid = total_chunks / (block * UNROLL);

    embedding_gather_kernel<<<grid, block>>>(indices, weight, out, total_chunks);
}